// round 10
// baseline (speedup 1.0000x reference)
#include <cuda_runtime.h>
#include <cuda_fp16.h>
#include <math.h>
#include <stdint.h>

#define T_SEQ 256
#define BATCH 64
#define HID   256
#define NGATE 2048              // 2 dirs * 4H
#define MROWS (T_SEQ*BATCH)     // 16384
#define K0P   304               // padded input dim for layer 0 (300 -> 304)
#define NBLK_DIR 32             // persistent blocks per direction

// ---------------- scratch (device globals; no allocation allowed) ----------------
__device__ __half   g_x0h[(size_t)MROWS * K0P];     // embedded input, fp16, padded
__device__ __half   g_w0h[NGATE * K0P];             // padded wih0, fp16
__device__ __half   g_w1h[NGATE * 512];             // wih1, fp16
// gates layout: [blk(64)][t(256)][b(64)][g*8+u(32)] halves  (blk = dir*32 + j0/8)
__device__ __half   g_gatesh[(size_t)MROWS * NGATE];
// h history, fp16 fragment-native: [dir(2)][t(256)][8192 u32]
//   per (dir,t): 16 ktiles(16 units) x 4 btiles(16 b) x 128 u32 (m16n8k16 A-frag per lane)
__device__ uint32_t g_hb[(size_t)2 * T_SEQ * 8192];
__device__ unsigned g_bar[2 * T_SEQ];               // per-dir per-step barrier counters

// ---------------- numeric helpers ----------------
__device__ __forceinline__ uint32_t pk_h2(float lo, float hi) {
    __half2 h = __floats2half2_rn(lo, hi);
    return *(uint32_t*)&h;
}
__device__ __forceinline__ void mma16h(float* c, const uint32_t* a, const uint32_t* b) {
    asm volatile("mma.sync.aligned.m16n8k16.row.col.f32.f16.f16.f32 "
                 "{%0,%1,%2,%3},{%4,%5,%6,%7},{%8,%9},{%0,%1,%2,%3};"
                 : "+f"(c[0]), "+f"(c[1]), "+f"(c[2]), "+f"(c[3])
                 : "r"(a[0]), "r"(a[1]), "r"(a[2]), "r"(a[3]),
                   "r"(b[0]), "r"(b[1]));
}
__device__ __forceinline__ float tanha(float x) {
    float y; asm("tanh.approx.f32 %0, %1;" : "=f"(y) : "f"(x)); return y;
}
__device__ __forceinline__ float siga(float x) { return fmaf(0.5f, tanha(0.5f * x), 0.5f); }
__device__ __forceinline__ unsigned ld_acq(const unsigned* p) {
    unsigned v; asm volatile("ld.acquire.gpu.global.u32 %0, [%1];" : "=r"(v) : "l"(p)); return v;
}
__device__ __forceinline__ uint4 ldcg_u4(const uint4* p) {
    uint4 v;
    asm volatile("ld.global.cg.v4.u32 {%0,%1,%2,%3}, [%4];"
                 : "=r"(v.x), "=r"(v.y), "=r"(v.z), "=r"(v.w) : "l"(p));
    return v;
}

// ---------------- small kernels ----------------
__global__ void k_cvtw(const float* __restrict__ w0, const float* __restrict__ w1) {
    int n = blockIdx.x;
    if (n < NGATE) {
        __half* o = g_w0h + n * K0P;
        const float* s = w0 + n * 300;
        for (int k = threadIdx.x; k < K0P; k += blockDim.x)
            o[k] = (k < 300) ? __float2half(s[k]) : __half(0.f);
    } else {
        n -= NGATE;
        __half* o = g_w1h + n * 512;
        const float* s = w1 + n * 512;
        for (int k = threadIdx.x; k < 512; k += blockDim.x)
            o[k] = __float2half(s[k]);
    }
}
__global__ void k_embed(const int* __restrict__ inp, const float* __restrict__ emb) {
    int m = blockIdx.x;            // m = t*64 + b
    int t = m >> 6, b = m & 63;
    int idx = inp[b * T_SEQ + t];
    const float* e = emb + (size_t)idx * 300;
    __half* o = g_x0h + (size_t)m * K0P;
    for (int k = threadIdx.x; k < K0P; k += blockDim.x)
        o[k] = (k < 300) ? __float2half(e[k]) : __half(0.f);
}

// ---------------- GEMM epilogue: store to scan-friendly fp16 gates layout ----------
__device__ __forceinline__ void gates_store(float c[4][4][4], const float* bi,
                                            const float* bh, int m0, int n0,
                                            int warp_m, int warp_n, int lane) {
    uint32_t* gout = (uint32_t*)g_gatesh;
#pragma unroll
    for (int nt = 0; nt < 4; nt++) {
        int n = n0 + warp_n * 32 + nt * 8 + (lane & 3) * 2;
        int dir = n >> 10, g = (n >> 8) & 3, j = n & 255;
        int blk = dir * 32 + (j >> 3), u = j & 7;
        float b0 = bi[n] + bh[n], b1 = bi[n + 1] + bh[n + 1];
        int inner = g * 4 + (u >> 1);          // u32 index within 16
#pragma unroll
        for (int mt = 0; mt < 4; mt++) {
            int r0 = m0 + warp_m * 64 + mt * 16 + (lane >> 2);
            int t = r0 >> 6, bb = r0 & 63;
            size_t base = ((size_t)(blk * 256 + t) * 64);
            gout[(base + bb) * 16 + inner]     = pk_h2(c[mt][nt][0] + b0, c[mt][nt][1] + b1);
            gout[(base + bb + 8) * 16 + inner] = pk_h2(c[mt][nt][2] + b0, c[mt][nt][3] + b1);
        }
    }
}

// ---------------- fp16 GEMM, layer 0 (A = g_x0h via smem) ----------------
__global__ __launch_bounds__(256) void k_gemm0(const float* __restrict__ bi,
                                               const float* __restrict__ bh) {
    constexpr int K = K0P;
    constexpr int NST = K / 16;
    const __half* A = g_x0h;
    const __half* W = g_w0h;

    if (blockIdx.x == 0 && blockIdx.y == 0) {      // zero scan barriers
        g_bar[threadIdx.x] = 0u; g_bar[threadIdx.x + 256] = 0u;
    }

    __shared__ uint32_t As[2][1024];
    __shared__ uint32_t Bs[2][1024];

    const int tid = threadIdx.x, lane = tid & 31, wid = tid >> 5;
    const int m0 = blockIdx.y << 7, n0 = blockIdx.x << 7;
    const int warp_m = wid & 1, warp_n = wid >> 1;

    const __half *agp[2], *wgp[2];
    int aoff[2], boff[2];
#pragma unroll
    for (int e = 0; e < 2; e++) {
        int q = tid * 2 + e, row = q >> 2, kq = q & 3;
        agp[e] = A + (size_t)(m0 + row) * K + (kq << 2);
        wgp[e] = W + (size_t)(n0 + row) * K + (kq << 2);
        int p0 = kq * 2;
        aoff[e] = (((row >> 4) * 4 + (((row >> 3) & 1) | ((p0 >> 2) << 1))) << 5)
                + ((row & 7) << 2) + (p0 & 3);
        boff[e] = (((row >> 3) * 2 + (p0 >> 2)) << 5) + ((row & 7) << 2) + (p0 & 3);
    }

    float c[4][4][4];
#pragma unroll
    for (int i = 0; i < 4; i++)
#pragma unroll
        for (int j = 0; j < 4; j++)
#pragma unroll
            for (int q = 0; q < 4; q++) c[i][j][q] = 0.f;

#pragma unroll
    for (int e = 0; e < 2; e++) {
        *(uint2*)&As[0][aoff[e]] = *(const uint2*)agp[e];
        *(uint2*)&Bs[0][boff[e]] = *(const uint2*)wgp[e];
    }
    __syncthreads();

    int buf = 0;
#pragma unroll 1
    for (int s = 0; s < NST; s++) {
        uint2 va[2], vb[2];
        const bool more = (s + 1) < NST;
        if (more) {
#pragma unroll
            for (int e = 0; e < 2; e++) {
                va[e] = *(const uint2*)(agp[e] + (s + 1) * 16);
                vb[e] = *(const uint2*)(wgp[e] + (s + 1) * 16);
            }
        }
        uint32_t af[4][4], bf[4][2];
#pragma unroll
        for (int mt = 0; mt < 4; mt++) {
            int tb = ((warp_m * 4 + mt) << 7) + lane;
#pragma unroll
            for (int r = 0; r < 4; r++) af[mt][r] = As[buf][tb + (r << 5)];
        }
#pragma unroll
        for (int nt = 0; nt < 4; nt++) {
            int tb = ((warp_n * 4 + nt) << 6) + lane;
            bf[nt][0] = Bs[buf][tb];
            bf[nt][1] = Bs[buf][tb + 32];
        }
#pragma unroll
        for (int mt = 0; mt < 4; mt++)
#pragma unroll
            for (int nt = 0; nt < 4; nt++)
                mma16h(c[mt][nt], af[mt], bf[nt]);

        if (more) {
            int nb = buf ^ 1;
#pragma unroll
            for (int e = 0; e < 2; e++) {
                *(uint2*)&As[nb][aoff[e]] = va[e];
                *(uint2*)&Bs[nb][boff[e]] = vb[e];
            }
            __syncthreads();
            buf = nb;
        }
    }
    gates_store(c, bi, bh, m0, n0, warp_m, warp_n, lane);
}

// ---------------- fp16 GEMM, layer 1 (A = fragment-native h history, no A smem) ----
__global__ __launch_bounds__(256) void k_gemm1(const float* __restrict__ bi,
                                               const float* __restrict__ bh) {
    constexpr int NST = 32;   // K = 512
    const __half* W = g_w1h;

    if (blockIdx.x == 0 && blockIdx.y == 0) {      // zero scan barriers
        g_bar[threadIdx.x] = 0u; g_bar[threadIdx.x + 256] = 0u;
    }

    __shared__ uint32_t Bs[2][1024];

    const int tid = threadIdx.x, lane = tid & 31, wid = tid >> 5;
    const int m0 = blockIdx.y << 7, n0 = blockIdx.x << 7;
    const int warp_m = wid & 1, warp_n = wid >> 1;

    const __half* wgp[2];
    int boff[2];
#pragma unroll
    for (int e = 0; e < 2; e++) {
        int q = tid * 2 + e, row = q >> 2, kq = q & 3;
        wgp[e] = W + (size_t)(n0 + row) * 512 + (kq << 2);
        int p0 = kq * 2;
        boff[e] = (((row >> 3) * 2 + (p0 >> 2)) << 5) + ((row & 7) << 2) + (p0 & 3);
    }

    // A-fragment address: ktile kt (0..31): dir=kt>>4, ut=kt&15; mtile idx=warp_m*4+mt
    const int ty0 = 2 * blockIdx.y;
    auto aptr = [&](int kt, int mt) -> const uint4* {
        int idx = warp_m * 4 + mt;
        return (const uint4*)(g_hb
            + ((size_t)((kt >> 4) * 256 + ty0 + (idx >> 2)) << 13)
            + (((kt & 15) * 4 + (idx & 3)) << 7)) + lane;
    };

    float c[4][4][4];
#pragma unroll
    for (int i = 0; i < 4; i++)
#pragma unroll
        for (int j = 0; j < 4; j++)
#pragma unroll
            for (int q = 0; q < 4; q++) c[i][j][q] = 0.f;

#pragma unroll
    for (int e = 0; e < 2; e++)
        *(uint2*)&Bs[0][boff[e]] = *(const uint2*)wgp[e];
    uint4 afc[4];
#pragma unroll
    for (int mt = 0; mt < 4; mt++) afc[mt] = __ldg(aptr(0, mt));
    __syncthreads();

    int buf = 0;
#pragma unroll 1
    for (int s = 0; s < NST; s++) {
        uint2 vb[2];
        uint4 afn[4];
        const bool more = (s + 1) < NST;
        if (more) {
#pragma unroll
            for (int e = 0; e < 2; e++) vb[e] = *(const uint2*)(wgp[e] + (s + 1) * 16);
#pragma unroll
            for (int mt = 0; mt < 4; mt++) afn[mt] = __ldg(aptr(s + 1, mt));
        }
        uint32_t bf[4][2];
#pragma unroll
        for (int nt = 0; nt < 4; nt++) {
            int tb = ((warp_n * 4 + nt) << 6) + lane;
            bf[nt][0] = Bs[buf][tb];
            bf[nt][1] = Bs[buf][tb + 32];
        }
#pragma unroll
        for (int mt = 0; mt < 4; mt++) {
            uint32_t af[4] = { afc[mt].x, afc[mt].y, afc[mt].z, afc[mt].w };
#pragma unroll
            for (int nt = 0; nt < 4; nt++)
                mma16h(c[mt][nt], af, bf[nt]);
        }
        if (more) {
            int nb = buf ^ 1;
#pragma unroll
            for (int e = 0; e < 2; e++) *(uint2*)&Bs[nb][boff[e]] = vb[e];
            __syncthreads();
            buf = nb;
#pragma unroll
            for (int mt = 0; mt < 4; mt++) afc[mt] = afn[mt];
        }
    }
    gates_store(c, bi, bh, m0, n0, warp_m, warp_n, lane);
}

// ---------------- recurrent scan: fp16 tc persistent kernel, history exchange ------
// 64 blocks (32/dir). Block: 8 hidden units (32 gate rows) x 64 batches.
// Warp 0 polls the global per-dir counter (single coalesced request); fans out via
// an smem flag (st.release.cta / ld.acquire.cta) so only 32 pollers/dir hit L2.
__global__ __launch_bounds__(256, 1) void k_lstm(const float* __restrict__ whh) {
    __shared__ uint32_t gsm[2][64 * 17];  // double-buffered gin staging, pad-17
    __shared__ float psum[4 * 32 * 68];   // k-split partials [kq][nn][b], nn = u*4+g
    __shared__ unsigned sflag;            // step fan-out flag

    const int tid = threadIdx.x, lane = tid & 31, wid = tid >> 5;
    const int bid = blockIdx.x;
    const int dir = bid >> 5;
    const int j0  = (bid & 31) << 3;      // 8 hidden units per block
    const int mh  = wid >> 2;             // batch half
    const int kq  = wid & 3;              // k quarter
    unsigned* barp = g_bar + dir * 256;

    if (tid == 0) sflag = 0u;
    uint32_t sfa = (uint32_t)__cvta_generic_to_shared(&sflag);

    // persistent B fragments: W^T slice, fp16, 32 regs.  psum row nn: gate=nn&3, unit=nn>>2
    uint32_t bfr[4][4][2];
    {
        const int nr = lane >> 2, kl2 = (lane & 3) * 2;
#pragma unroll
        for (int nt = 0; nt < 4; nt++) {
            int nn = nt * 8 + nr;
            int row = dir * 1024 + (nn & 3) * 256 + j0 + (nn >> 2);
            const float* wr = whh + (size_t)row * 256 + kq * 64 + kl2;
#pragma unroll
            for (int kt = 0; kt < 4; kt++) {
                bfr[nt][kt][0] = pk_h2(wr[kt * 16],     wr[kt * 16 + 1]);
                bfr[nt][kt][1] = pk_h2(wr[kt * 16 + 8], wr[kt * 16 + 9]);
            }
        }
    }

    // gate-math mapping: thread (p, b) owns units j0+2p, j0+2p+1 for batch b
    const int p = tid >> 6, b = tid & 63;
    float cst0 = 0.f, cst1 = 0.f;
    // publish address (one u32 per thread per step; fragment slot math)
    uint32_t* pub = g_hb + ((size_t)(dir * 256) << 13)
                  + (((j0 >> 4) * 4 + (b >> 4)) << 7)
                  + (((b & 7) << 2) + p) * 4
                  + (((b & 8) >> 3) + ((j0 & 8) >> 2));
    const uint4* gb4 = (const uint4*)g_gatesh + (size_t)(bid * 256) * 256;

    // prologue: stage gin(0)
    {
        uint4 g4 = __ldg(gb4 + tid);
        uint32_t* gd = gsm[0] + (tid >> 2) * 17 + (tid & 3) * 4;
        gd[0] = g4.x; gd[1] = g4.y; gd[2] = g4.z; gd[3] = g4.w;
    }

    for (int t = 0; t < T_SEQ; t++) {
        // prefetch gin(t+1) and stage it immediately (safe: all warps passed the
        // previous step's post-publish barrier; readers of this buffer are gone)
        {
            int tn = (t + 1 < T_SEQ) ? t + 1 : T_SEQ - 1;
            uint4 g4 = __ldg(gb4 + tn * 256 + tid);
            uint32_t* gd = gsm[(t + 1) & 1] + (tid >> 2) * 17 + (tid & 3) * 4;
            gd[0] = g4.x; gd[1] = g4.y; gd[2] = g4.z; gd[3] = g4.w;
        }

        if (t > 0) {
            // warp 0: sole global poller; fans out via smem flag
            if (wid == 0) {
                while (ld_acq(&barp[t - 1]) < NBLK_DIR) {}
                if (lane == 0)
                    asm volatile("st.release.cta.shared.u32 [%0], %1;"
                                 :: "r"(sfa), "r"((unsigned)t) : "memory");
            } else {
                unsigned v;
                do {
                    asm volatile("ld.acquire.cta.shared.u32 %0, [%1];"
                                 : "=r"(v) : "r"(sfa) : "memory");
                } while (v < (unsigned)t);
            }

            // load A fragments: 8 coalesced LDG.128/warp (32KB/block, L2)
            const uint4* hb = (const uint4*)(g_hb + ((size_t)(dir * 256 + t - 1) << 13));
            uint4 aq[2][4];
#pragma unroll
            for (int kt = 0; kt < 4; kt++)
#pragma unroll
                for (int mt = 0; mt < 2; mt++)
                    aq[mt][kt] = ldcg_u4(hb + (((kq * 4 + kt) * 4 + mh * 2 + mt) << 5) + lane);

            float acc[2][4][4];
#pragma unroll
            for (int i = 0; i < 2; i++)
#pragma unroll
                for (int j = 0; j < 4; j++)
#pragma unroll
                    for (int q = 0; q < 4; q++) acc[i][j][q] = 0.f;
#pragma unroll
            for (int kt = 0; kt < 4; kt++)
#pragma unroll
                for (int mt = 0; mt < 2; mt++) {
                    uint32_t au[4] = { aq[mt][kt].x, aq[mt][kt].y, aq[mt][kt].z, aq[mt][kt].w };
#pragma unroll
                    for (int nt = 0; nt < 4; nt++)
                        mma16h(acc[mt][nt], au, bfr[nt][kt]);
                }
#pragma unroll
            for (int mt = 0; mt < 2; mt++)
#pragma unroll
                for (int nt = 0; nt < 4; nt++) {
                    int n0 = nt * 8 + (lane & 3) * 2;
                    int bb = mh * 32 + mt * 16 + (lane >> 2);
                    float* pp = psum + (kq * 32 + n0) * 68 + bb;
                    pp[0]      = acc[mt][nt][0];
                    pp[68]     = acc[mt][nt][1];
                    pp[8]      = acc[mt][nt][2];
                    pp[68 + 8] = acc[mt][nt][3];
                }
        }
        __syncthreads();   // psum + gsm(t) ready

        // gate math for units 2p, 2p+1 of batch b
        float v[4][2];
#pragma unroll
        for (int g = 0; g < 4; g++) {
            __half2 hv = *(__half2*)&gsm[t & 1][b * 17 + g * 4 + p];
            float2 f2 = __half22float2(hv);
            v[g][0] = f2.x; v[g][1] = f2.y;
        }
        if (t > 0) {
            // psum row for (unit u, gate g) is nn = u*4 + g
#pragma unroll
            for (int g = 0; g < 4; g++) {
                int r0 = 8 * p + g;
#pragma unroll
                for (int q = 0; q < 4; q++) {
                    v[g][0] += psum[(q * 32 + r0) * 68 + b];
                    v[g][1] += psum[(q * 32 + r0 + 4) * 68 + b];
                }
            }
        }
        float h0, h1;
        {
            float ci = siga(v[0][0]), cf = siga(v[1][0]), cg = tanha(v[2][0]), co = siga(v[3][0]);
            cst0 = cf * cst0 + ci * cg;
            h0 = co * tanha(cst0);
            ci = siga(v[0][1]); cf = siga(v[1][1]); cg = tanha(v[2][1]); co = siga(v[3][1]);
            cst1 = cf * cst1 + ci * cg;
            h1 = co * tanha(cst1);
        }
        // publish: one fragment u32 directly into history (exchange + layer output)
        pub[(size_t)t << 13] = pk_h2(h0, h1);
        __syncthreads();   // all publish STGs issued
        if (tid == 0 && t < T_SEQ - 1)
            asm volatile("red.release.gpu.global.add.u32 [%0], 1;"
                         :: "l"(&barp[t]) : "memory");
    }
}

// ---------------- classifier: gather from layer-1 history ----------------
__global__ void k_clf(const int* __restrict__ tidx, const float* __restrict__ cw,
                      const float* __restrict__ cb, float* __restrict__ out) {
    __shared__ float red[128];
    int b = blockIdx.x;
    int t = tidx[b];
    const __half* hist = (const __half*)g_hb;
    float s = 0.f;
    for (int f = threadIdx.x; f < 512; f += 128) {
        int dir = f >> 8, u = f & 255;
        int ut = u >> 4, k16 = u & 15;
        int l = ((b & 7) << 2) + ((k16 & 7) >> 1);
        int sl = ((b & 8) >> 3) + ((k16 & 8) >> 2);
        size_t u32i = ((size_t)(dir * 256 + t) << 13) + (((ut << 2) + (b >> 4)) << 7)
                    + l * 4 + sl;
        s += __half2float(hist[u32i * 2 + (k16 & 1)]) * cw[f];
    }
    red[threadIdx.x] = s;
    __syncthreads();
    for (int off = 64; off > 0; off >>= 1) {
        if (threadIdx.x < off) red[threadIdx.x] += red[threadIdx.x + off];
        __syncthreads();
    }
    if (threadIdx.x == 0) out[b] = 1.f / (1.f + expf(-(red[0] + cb[0])));
}

// ---------------- host ----------------
extern "C" void kernel_launch(void* const* d_in, const int* in_sizes, int n_in,
                              void* d_out, int out_size) {
    const int*   inp  = (const int*)  d_in[0];
    const int*   tidx = (const int*)  d_in[1];
    const float* emb  = (const float*)d_in[2];
    const float* wih0 = (const float*)d_in[3];
    const float* whh0 = (const float*)d_in[4];
    const float* bih0 = (const float*)d_in[5];
    const float* bhh0 = (const float*)d_in[6];
    const float* wih1 = (const float*)d_in[7];
    const float* whh1 = (const float*)d_in[8];
    const float* bih1 = (const float*)d_in[9];
    const float* bhh1 = (const float*)d_in[10];
    const float* clfw = (const float*)d_in[11];
    const float* clfb = (const float*)d_in[12];
    float* out = (float*)d_out;

    // layer 0
    k_cvtw<<<2 * NGATE, 128>>>(wih0, wih1);
    k_embed<<<MROWS, 128>>>(inp, emb);
    k_gemm0<<<dim3(16, 128), 256>>>(bih0, bhh0);     // also zeros g_bar
    k_lstm<<<2 * NBLK_DIR, 256>>>(whh0);             // writes h history

    // layer 1 (GEMM A = layer-0 history fragments)
    k_gemm1<<<dim3(16, 128), 256>>>(bih1, bhh1);     // also zeros g_bar
    k_lstm<<<2 * NBLK_DIR, 256>>>(whh1);             // overwrites history with layer-1 h

    // classifier gathers from layer-1 history
    k_clf<<<BATCH, 128>>>(tidx, clfw, clfb, out);
}

// round 13
// speedup vs baseline: 1.6689x; 1.6689x over previous
#include <cuda_runtime.h>
#include <cuda_fp16.h>
#include <math.h>
#include <stdint.h>

#define T_SEQ 256
#define BATCH 64
#define HID   256
#define NGATE 2048              // 2 dirs * 4H
#define MROWS (T_SEQ*BATCH)     // 16384
#define K0P   304               // padded input dim for layer 0 (300 -> 304)
#define NBLK_DIR 32             // lstm blocks per direction

// role bid ranges in the fused kernel
#define LSTM0_BASE 0
#define GEMM0_BASE 64
#define LSTM1_BASE 2112
#define GEMM1_BASE 2176
#define TOTAL_BLKS 4224

// ---------------- scratch (device globals; no allocation allowed) ----------------
__device__ __half   g_x0h[(size_t)MROWS * K0P];     // embedded input, fp16, padded
__device__ __half   g_w0h[NGATE * K0P];             // padded wih0, fp16
__device__ __half   g_w1h[NGATE * 512];             // wih1, fp16
// gates layout: [blk(64)][t(256)][b(64)][g*8+u(32)] halves  (blk = dir*32 + j0/8)
__device__ __half   g_gates0h[(size_t)MROWS * NGATE];
__device__ __half   g_gates1h[(size_t)MROWS * NGATE];
// h history, fp16 fragment-native: [dir(2)][t(256)][8192 u32]
__device__ uint32_t g_hb0[(size_t)2 * T_SEQ * 8192];
__device__ uint32_t g_hb1[(size_t)2 * T_SEQ * 8192];
// sync: [0..511] hbar0[dir*256+t], [512..1023] hbar1, [1024..1151] gcnt0[by], [1152..1279] gcnt1[by]
__device__ unsigned g_sync[1280];

// ---------------- numeric helpers ----------------
__device__ __forceinline__ uint32_t pk_h2(float lo, float hi) {
    __half2 h = __floats2half2_rn(lo, hi);
    return *(uint32_t*)&h;
}
__device__ __forceinline__ void mma16h(float* c, const uint32_t* a, const uint32_t* b) {
    asm volatile("mma.sync.aligned.m16n8k16.row.col.f32.f16.f16.f32 "
                 "{%0,%1,%2,%3},{%4,%5,%6,%7},{%8,%9},{%0,%1,%2,%3};"
                 : "+f"(c[0]), "+f"(c[1]), "+f"(c[2]), "+f"(c[3])
                 : "r"(a[0]), "r"(a[1]), "r"(a[2]), "r"(a[3]),
                   "r"(b[0]), "r"(b[1]));
}
__device__ __forceinline__ float tanha(float x) {
    float y; asm("tanh.approx.f32 %0, %1;" : "=f"(y) : "f"(x)); return y;
}
__device__ __forceinline__ float siga(float x) { return fmaf(0.5f, tanha(0.5f * x), 0.5f); }
__device__ __forceinline__ unsigned ld_acq(const unsigned* p) {
    unsigned v; asm volatile("ld.acquire.gpu.global.u32 %0, [%1];" : "=r"(v) : "l"(p)); return v;
}
__device__ __forceinline__ void red_rel(unsigned* p) {
    asm volatile("red.release.gpu.global.add.u32 [%0], 1;" :: "l"(p) : "memory");
}
__device__ __forceinline__ uint4 ldcg_u4(const uint4* p) {
    uint4 v;
    asm volatile("ld.global.cg.v4.u32 {%0,%1,%2,%3}, [%4];"
                 : "=r"(v.x), "=r"(v.y), "=r"(v.z), "=r"(v.w) : "l"(p));
    return v;
}

// ---------------- small kernels ----------------
__global__ void k_cvtw(const float* __restrict__ w0, const float* __restrict__ w1) {
    int n = blockIdx.x;
    if (n < NGATE) {
        __half* o = g_w0h + n * K0P;
        const float* s = w0 + n * 300;
        for (int k = threadIdx.x; k < K0P; k += blockDim.x)
            o[k] = (k < 300) ? __float2half(s[k]) : __half(0.f);
    } else {
        n -= NGATE;
        __half* o = g_w1h + n * 512;
        const float* s = w1 + n * 512;
        for (int k = threadIdx.x; k < 512; k += blockDim.x)
            o[k] = __float2half(s[k]);
    }
}
__global__ void k_embed(const int* __restrict__ inp, const float* __restrict__ emb) {
    if (blockIdx.x == 0)                      // zero all sync counters each run
        for (int i = threadIdx.x; i < 1280; i += blockDim.x) g_sync[i] = 0u;
    int m = blockIdx.x;            // m = t*64 + b
    int t = m >> 6, b = m & 63;
    int idx = inp[b * T_SEQ + t];
    const float* e = emb + (size_t)idx * 300;
    __half* o = g_x0h + (size_t)m * K0P;
    for (int k = threadIdx.x; k < K0P; k += blockDim.x)
        o[k] = (k < 300) ? __float2half(e[k]) : __half(0.f);
}

// ---------------- GEMM epilogue: store to scan-friendly fp16 gates layout ----------
__device__ __forceinline__ void gates_store(float c[4][4][4], const float* bi,
                                            const float* bh, int m0, int n0,
                                            int warp_m, int warp_n, int lane,
                                            uint32_t* gout) {
#pragma unroll
    for (int nt = 0; nt < 4; nt++) {
        int n = n0 + warp_n * 32 + nt * 8 + (lane & 3) * 2;
        int dir = n >> 10, g = (n >> 8) & 3, j = n & 255;
        int blk = dir * 32 + (j >> 3), u = j & 7;
        float b0 = bi[n] + bh[n], b1 = bi[n + 1] + bh[n + 1];
        int inner = g * 4 + (u >> 1);          // u32 index within 16
#pragma unroll
        for (int mt = 0; mt < 4; mt++) {
            int r0 = m0 + warp_m * 64 + mt * 16 + (lane >> 2);
            int t = r0 >> 6, bb = r0 & 63;
            size_t base = ((size_t)(blk * 256 + t) * 64);
            gout[(base + bb) * 16 + inner]     = pk_h2(c[mt][nt][0] + b0, c[mt][nt][1] + b1);
            gout[(base + bb + 8) * 16 + inner] = pk_h2(c[mt][nt][2] + b0, c[mt][nt][3] + b1);
        }
    }
}

// ---------------- role: fp16 GEMM layer 0 (A = g_x0h via smem) ----------------
__device__ void gemm0_role(int gb, const float* bi, const float* bh, char* sbuf) {
    constexpr int K = K0P;
    constexpr int NST = K / 16;
    const __half* A = g_x0h;
    const __half* W = g_w0h;
    uint32_t* As = (uint32_t*)sbuf;       // [2][1024]
    uint32_t* Bs = As + 2048;             // [2][1024]

    const int tid = threadIdx.x, lane = tid & 31, wid = tid >> 5;
    const int by = gb >> 4, bx = gb & 15;
    const int m0 = by << 7, n0 = bx << 7;
    const int warp_m = wid & 1, warp_n = wid >> 1;

    const __half *agp[2], *wgp[2];
    int aoff[2], boff[2];
#pragma unroll
    for (int e = 0; e < 2; e++) {
        int q = tid * 2 + e, row = q >> 2, kq = q & 3;
        agp[e] = A + (size_t)(m0 + row) * K + (kq << 2);
        wgp[e] = W + (size_t)(n0 + row) * K + (kq << 2);
        int p0 = kq * 2;
        aoff[e] = (((row >> 4) * 4 + (((row >> 3) & 1) | ((p0 >> 2) << 1))) << 5)
                + ((row & 7) << 2) + (p0 & 3);
        boff[e] = (((row >> 3) * 2 + (p0 >> 2)) << 5) + ((row & 7) << 2) + (p0 & 3);
    }

    float c[4][4][4];
#pragma unroll
    for (int i = 0; i < 4; i++)
#pragma unroll
        for (int j = 0; j < 4; j++)
#pragma unroll
            for (int q = 0; q < 4; q++) c[i][j][q] = 0.f;

#pragma unroll
    for (int e = 0; e < 2; e++) {
        *(uint2*)&As[aoff[e]] = *(const uint2*)agp[e];
        *(uint2*)&Bs[boff[e]] = *(const uint2*)wgp[e];
    }
    __syncthreads();

    int buf = 0;
#pragma unroll 1
    for (int s = 0; s < NST; s++) {
        uint2 va[2], vb[2];
        const bool more = (s + 1) < NST;
        if (more) {
#pragma unroll
            for (int e = 0; e < 2; e++) {
                va[e] = *(const uint2*)(agp[e] + (s + 1) * 16);
                vb[e] = *(const uint2*)(wgp[e] + (s + 1) * 16);
            }
        }
        uint32_t af[4][4], bf[4][2];
#pragma unroll
        for (int mt = 0; mt < 4; mt++) {
            int tb = buf * 1024 + ((warp_m * 4 + mt) << 7) + lane;
#pragma unroll
            for (int r = 0; r < 4; r++) af[mt][r] = As[tb + (r << 5)];
        }
#pragma unroll
        for (int nt = 0; nt < 4; nt++) {
            int tb = buf * 1024 + ((warp_n * 4 + nt) << 6) + lane;
            bf[nt][0] = Bs[tb];
            bf[nt][1] = Bs[tb + 32];
        }
#pragma unroll
        for (int mt = 0; mt < 4; mt++)
#pragma unroll
            for (int nt = 0; nt < 4; nt++)
                mma16h(c[mt][nt], af[mt], bf[nt]);

        if (more) {
            int nb = buf ^ 1;
#pragma unroll
            for (int e = 0; e < 2; e++) {
                *(uint2*)&As[nb * 1024 + aoff[e]] = va[e];
                *(uint2*)&Bs[nb * 1024 + boff[e]] = vb[e];
            }
            __syncthreads();
            buf = nb;
        }
    }
    gates_store(c, bi, bh, m0, n0, warp_m, warp_n, lane, (uint32_t*)g_gates0h);
    __syncthreads();                       // all stores issued block-wide
    if (tid == 0) red_rel(&g_sync[1024 + by]);
}

// ---------------- role: fp16 GEMM layer 1 (A = h0 history fragments) ----------------
__device__ void gemm1_role(int gb, const float* bi, const float* bh, char* sbuf) {
    constexpr int NST = 32;   // K = 512
    const __half* W = g_w1h;
    uint32_t* Bs = (uint32_t*)sbuf;       // [2][1024]

    const int tid = threadIdx.x, lane = tid & 31, wid = tid >> 5;
    const int by = gb >> 4, bx = gb & 15;
    const int m0 = by << 7, n0 = bx << 7;
    const int warp_m = wid & 1, warp_n = wid >> 1;

    // wait for h0 of both dirs through t = 2by+1
    if (tid == 0) {
        while (ld_acq(&g_sync[2 * by + 1]) < NBLK_DIR) {}
        while (ld_acq(&g_sync[256 + 2 * by + 1]) < NBLK_DIR) {}
    }
    __syncthreads();

    const __half* wgp[2];
    int boff[2];
#pragma unroll
    for (int e = 0; e < 2; e++) {
        int q = tid * 2 + e, row = q >> 2, kq = q & 3;
        wgp[e] = W + (size_t)(n0 + row) * 512 + (kq << 2);
        int p0 = kq * 2;
        boff[e] = (((row >> 3) * 2 + (p0 >> 2)) << 5) + ((row & 7) << 2) + (p0 & 3);
    }

    const int ty0 = 2 * by;
    auto aptr = [&](int kt, int mt) -> const uint4* {
        int idx = warp_m * 4 + mt;
        return (const uint4*)(g_hb0
            + ((size_t)((kt >> 4) * 256 + ty0 + (idx >> 2)) << 13)
            + (((kt & 15) * 4 + (idx & 3)) << 7)) + lane;
    };

    float c[4][4][4];
#pragma unroll
    for (int i = 0; i < 4; i++)
#pragma unroll
        for (int j = 0; j < 4; j++)
#pragma unroll
            for (int q = 0; q < 4; q++) c[i][j][q] = 0.f;

#pragma unroll
    for (int e = 0; e < 2; e++)
        *(uint2*)&Bs[boff[e]] = *(const uint2*)wgp[e];
    uint4 afc[4];
#pragma unroll
    for (int mt = 0; mt < 4; mt++) afc[mt] = ldcg_u4(aptr(0, mt));
    __syncthreads();

    int buf = 0;
#pragma unroll 1
    for (int s = 0; s < NST; s++) {
        uint2 vb[2];
        uint4 afn[4];
        const bool more = (s + 1) < NST;
        if (more) {
#pragma unroll
            for (int e = 0; e < 2; e++) vb[e] = *(const uint2*)(wgp[e] + (s + 1) * 16);
#pragma unroll
            for (int mt = 0; mt < 4; mt++) afn[mt] = ldcg_u4(aptr(s + 1, mt));
        }
        uint32_t bf[4][2];
#pragma unroll
        for (int nt = 0; nt < 4; nt++) {
            int tb = buf * 1024 + ((warp_n * 4 + nt) << 6) + lane;
            bf[nt][0] = Bs[tb];
            bf[nt][1] = Bs[tb + 32];
        }
#pragma unroll
        for (int mt = 0; mt < 4; mt++) {
            uint32_t af[4] = { afc[mt].x, afc[mt].y, afc[mt].z, afc[mt].w };
#pragma unroll
            for (int nt = 0; nt < 4; nt++)
                mma16h(c[mt][nt], af, bf[nt]);
        }
        if (more) {
            int nb = buf ^ 1;
#pragma unroll
            for (int e = 0; e < 2; e++) *(uint2*)&Bs[nb * 1024 + boff[e]] = vb[e];
            __syncthreads();
            buf = nb;
#pragma unroll
            for (int mt = 0; mt < 4; mt++) afc[mt] = afn[mt];
        }
    }
    gates_store(c, bi, bh, m0, n0, warp_m, warp_n, lane, (uint32_t*)g_gates1h);
    __syncthreads();
    if (tid == 0) red_rel(&g_sync[1152 + by]);
}

// ---------------- role: recurrent scan (R8-proven counter barrier) ----------------
__device__ void lstm_role(int layer, int lbid, const float* __restrict__ whh, char* sbuf) {
    uint32_t* gsm = (uint32_t*)sbuf;                 // [2][64*17]
    float* psum = (float*)(sbuf + 2 * 1088 * 4);     // [4*32*68]

    const int tid = threadIdx.x, lane = tid & 31, wid = tid >> 5;
    const int dir = lbid >> 5;
    const int j0  = (lbid & 31) << 3;     // 8 hidden units per block
    const int mh  = wid >> 2;             // batch half
    const int kq  = wid & 3;              // k quarter
    unsigned* barp = g_sync + layer * 512 + dir * 256;
    unsigned* gcnt = g_sync + 1024 + layer * 128;
    uint32_t* hist = layer ? g_hb1 : g_hb0;

    // persistent B fragments: W^T slice, fp16, 32 regs.  psum row nn = u*4 + g
    uint32_t bfr[4][4][2];
    {
        const int nr = lane >> 2, kl2 = (lane & 3) * 2;
#pragma unroll
        for (int nt = 0; nt < 4; nt++) {
            int nn = nt * 8 + nr;
            int row = dir * 1024 + (nn & 3) * 256 + j0 + (nn >> 2);
            const float* wr = whh + (size_t)row * 256 + kq * 64 + kl2;
#pragma unroll
            for (int kt = 0; kt < 4; kt++) {
                bfr[nt][kt][0] = pk_h2(wr[kt * 16],     wr[kt * 16 + 1]);
                bfr[nt][kt][1] = pk_h2(wr[kt * 16 + 8], wr[kt * 16 + 9]);
            }
        }
    }

    const int p = tid >> 6, b = tid & 63;
    float cst0 = 0.f, cst1 = 0.f;
    uint32_t* pub = hist + ((size_t)(dir * 256) << 13)
                  + (((j0 >> 4) * 4 + (b >> 4)) << 7)
                  + (((b & 7) << 2) + p) * 4
                  + (((b & 8) >> 3) + ((j0 & 8) >> 2));
    const uint4* gb4 = (const uint4*)(layer ? g_gates1h : g_gates0h)
                     + (size_t)(lbid * 256) * 256;

    // prologue: wait for gates(t=0,1) then stage gin(0)
    if (tid == 0) { while (ld_acq(&gcnt[0]) < 16) {} }
    __syncthreads();
    {
        uint4 g4 = __ldg(gb4 + tid);
        uint32_t* gd = gsm + (tid >> 2) * 17 + (tid & 3) * 4;
        gd[0] = g4.x; gd[1] = g4.y; gd[2] = g4.z; gd[3] = g4.w;
    }

    for (int t = 0; t < T_SEQ; t++) {
        // ensure gates for t+1 are produced (new t-pair every odd t).
        // FIX vs R11: guard t+1 < T_SEQ — at t=255 the index (t+1)>>1 = 128 is
        // out of the 128-entry counter array (that OOB spin was the R11 hang).
        if ((t & 1) && (t + 1) < T_SEQ) {
            if (tid == 0) { while (ld_acq(&gcnt[(t + 1) >> 1]) < 16) {} }
            __syncthreads();
        }
        // prefetch gin(t+1) and stage into the other buffer
        {
            int tn = (t + 1 < T_SEQ) ? t + 1 : T_SEQ - 1;
            uint4 g4 = __ldg(gb4 + tn * 256 + tid);
            uint32_t* gd = gsm + ((t + 1) & 1) * 1088 + (tid >> 2) * 17 + (tid & 3) * 4;
            gd[0] = g4.x; gd[1] = g4.y; gd[2] = g4.z; gd[3] = g4.w;
        }

        if (t > 0) {
            // wait for all dir-mates to publish h(t-1) (R8 all-thread poll)
            while (ld_acq(&barp[t - 1]) < NBLK_DIR) {}
            const uint4* hb = (const uint4*)(hist + ((size_t)(dir * 256 + t - 1) << 13));
            uint4 aq[2][4];
#pragma unroll
            for (int kt = 0; kt < 4; kt++)
#pragma unroll
                for (int mt = 0; mt < 2; mt++)
                    aq[mt][kt] = ldcg_u4(hb + (((kq * 4 + kt) * 4 + mh * 2 + mt) << 5) + lane);

            float acc[2][4][4];
#pragma unroll
            for (int i = 0; i < 2; i++)
#pragma unroll
                for (int j = 0; j < 4; j++)
#pragma unroll
                    for (int q = 0; q < 4; q++) acc[i][j][q] = 0.f;
#pragma unroll
            for (int kt = 0; kt < 4; kt++)
#pragma unroll
                for (int mt = 0; mt < 2; mt++) {
                    uint32_t au[4] = { aq[mt][kt].x, aq[mt][kt].y, aq[mt][kt].z, aq[mt][kt].w };
#pragma unroll
                    for (int nt = 0; nt < 4; nt++)
                        mma16h(acc[mt][nt], au, bfr[nt][kt]);
                }
#pragma unroll
            for (int mt = 0; mt < 2; mt++)
#pragma unroll
                for (int nt = 0; nt < 4; nt++) {
                    int n0 = nt * 8 + (lane & 3) * 2;
                    int bb = mh * 32 + mt * 16 + (lane >> 2);
                    float* pp = psum + (kq * 32 + n0) * 68 + bb;
                    pp[0]      = acc[mt][nt][0];
                    pp[68]     = acc[mt][nt][1];
                    pp[8]      = acc[mt][nt][2];
                    pp[68 + 8] = acc[mt][nt][3];
                }
        }
        __syncthreads();   // psum + gsm(t) ready

        // gate math for units 2p, 2p+1 of batch b
        float v[4][2];
#pragma unroll
        for (int g = 0; g < 4; g++) {
            __half2 hv = *(__half2*)&gsm[(t & 1) * 1088 + b * 17 + g * 4 + p];
            float2 f2 = __half22float2(hv);
            v[g][0] = f2.x; v[g][1] = f2.y;
        }
        if (t > 0) {
            // psum row for (unit u, gate g): nn = u*4 + g; units 2p and 2p+1
#pragma unroll
            for (int g = 0; g < 4; g++) {
                int r0 = 8 * p + g;
#pragma unroll
                for (int q = 0; q < 4; q++) {
                    v[g][0] += psum[(q * 32 + r0) * 68 + b];
                    v[g][1] += psum[(q * 32 + r0 + 4) * 68 + b];
                }
            }
        }
        float h0, h1;
        {
            float ci = siga(v[0][0]), cf = siga(v[1][0]), cg = tanha(v[2][0]), co = siga(v[3][0]);
            cst0 = cf * cst0 + ci * cg;
            h0 = co * tanha(cst0);
            ci = siga(v[0][1]); cf = siga(v[1][1]); cg = tanha(v[2][1]); co = siga(v[3][1]);
            cst1 = cf * cst1 + ci * cg;
            h1 = co * tanha(cst1);
        }
        pub[(size_t)t << 13] = pk_h2(h0, h1);
        __syncthreads();   // all publish STGs issued
        if (tid == 0) red_rel(&barp[t]);   // signal EVERY t (gemm1 needs t=255)
    }
}

// ---------------- fused pipeline kernel ----------------
__global__ __launch_bounds__(256, 2) void k_fused(const float* __restrict__ bih0,
                                                  const float* __restrict__ bhh0,
                                                  const float* __restrict__ bih1,
                                                  const float* __restrict__ bhh1,
                                                  const float* __restrict__ whh0,
                                                  const float* __restrict__ whh1) {
    __shared__ __align__(16) char sbuf[43520];
    const int bid = blockIdx.x;
    if (bid < GEMM0_BASE) {
        lstm_role(0, bid, whh0, sbuf);
    } else if (bid < LSTM1_BASE) {
        gemm0_role(bid - GEMM0_BASE, bih0, bhh0, sbuf);
    } else if (bid < GEMM1_BASE) {
        lstm_role(1, bid - LSTM1_BASE, whh1, sbuf);
    } else {
        gemm1_role(bid - GEMM1_BASE, bih1, bhh1, sbuf);
    }
}

// ---------------- classifier: gather from layer-1 history ----------------
__global__ void k_clf(const int* __restrict__ tidx, const float* __restrict__ cw,
                      const float* __restrict__ cb, float* __restrict__ out) {
    __shared__ float red[128];
    int b = blockIdx.x;
    int t = tidx[b];
    const __half* hist = (const __half*)g_hb1;
    float s = 0.f;
    for (int f = threadIdx.x; f < 512; f += 128) {
        int dir = f >> 8, u = f & 255;
        int ut = u >> 4, k16 = u & 15;
        int l = ((b & 7) << 2) + ((k16 & 7) >> 1);
        int sl = ((b & 8) >> 3) + ((k16 & 8) >> 2);
        size_t u32i = ((size_t)(dir * 256 + t) << 13) + (((ut << 2) + (b >> 4)) << 7)
                    + l * 4 + sl;
        s += __half2float(hist[u32i * 2 + (k16 & 1)]) * cw[f];
    }
    red[threadIdx.x] = s;
    __syncthreads();
    for (int off = 64; off > 0; off >>= 1) {
        if (threadIdx.x < off) red[threadIdx.x] += red[threadIdx.x + off];
        __syncthreads();
    }
    if (threadIdx.x == 0) out[b] = 1.f / (1.f + expf(-(red[0] + cb[0])));
}

// ---------------- host ----------------
extern "C" void kernel_launch(void* const* d_in, const int* in_sizes, int n_in,
                              void* d_out, int out_size) {
    const int*   inp  = (const int*)  d_in[0];
    const int*   tidx = (const int*)  d_in[1];
    const float* emb  = (const float*)d_in[2];
    const float* wih0 = (const float*)d_in[3];
    const float* whh0 = (const float*)d_in[4];
    const float* bih0 = (const float*)d_in[5];
    const float* bhh0 = (const float*)d_in[6];
    const float* wih1 = (const float*)d_in[7];
    const float* whh1 = (const float*)d_in[8];
    const float* bih1 = (const float*)d_in[9];
    const float* bhh1 = (const float*)d_in[10];
    const float* clfw = (const float*)d_in[11];
    const float* clfb = (const float*)d_in[12];
    float* out = (float*)d_out;

    k_cvtw<<<2 * NGATE, 128>>>(wih0, wih1);
    k_embed<<<MROWS, 128>>>(inp, emb);        // also zeros g_sync
    // single fused pipeline: lstm0 | gemm0 | lstm1 | gemm1, counter-chained
    k_fused<<<TOTAL_BLKS, 256>>>(bih0, bhh0, bih1, bhh1, whh0, whh1);
    k_clf<<<BATCH, 128>>>(tidx, clfw, clfb, out);
}

// round 14
// speedup vs baseline: 1.6952x; 1.0157x over previous
#include <cuda_runtime.h>
#include <cuda_fp16.h>
#include <math.h>
#include <stdint.h>

#define T_SEQ 256
#define BATCH 64
#define HID   256
#define NGATE 2048              // 2 dirs * 4H
#define MROWS (T_SEQ*BATCH)     // 16384
#define K0P   304               // padded input dim for layer 0 (300 -> 304)
#define NBLK_DIR 32             // lstm blocks per direction

// fused-kernel bid map: [lstm0: 0-63][lstm1: 64-127][gemm, by-interleaved: 128+]
//   gemm group for t-pair 'by' = 32 bids: 16 gemm0 (bx 0-15) then 16 gemm1 (bx 0-15)
#define GEMM_BASE 128
#define TOTAL_BLKS (128 + 128 * 32)   // 4224

// ---------------- scratch (device globals; no allocation allowed) ----------------
__device__ __half   g_x0h[(size_t)MROWS * K0P];     // embedded input, fp16, padded
__device__ __half   g_w0h[NGATE * K0P];             // padded wih0, fp16
__device__ __half   g_w1h[NGATE * 512];             // wih1, fp16
// gates layout: [blk(64)][t(256)][b(64)][g*8+u(32)] halves  (blk = dir*32 + j0/8)
__device__ __half   g_gates0h[(size_t)MROWS * NGATE];
__device__ __half   g_gates1h[(size_t)MROWS * NGATE];
// h history, fp16 fragment-native: [dir(2)][t(256)][8192 u32]
__device__ uint32_t g_hb0[(size_t)2 * T_SEQ * 8192];
__device__ uint32_t g_hb1[(size_t)2 * T_SEQ * 8192];
// sync: [0..511] hbar0[dir*256+t], [512..1023] hbar1, [1024..1151] gcnt0[by], [1152..1279] gcnt1[by]
__device__ unsigned g_sync[1280];

// ---------------- numeric helpers ----------------
__device__ __forceinline__ uint32_t pk_h2(float lo, float hi) {
    __half2 h = __floats2half2_rn(lo, hi);
    return *(uint32_t*)&h;
}
__device__ __forceinline__ void mma16h(float* c, const uint32_t* a, const uint32_t* b) {
    asm volatile("mma.sync.aligned.m16n8k16.row.col.f32.f16.f16.f32 "
                 "{%0,%1,%2,%3},{%4,%5,%6,%7},{%8,%9},{%0,%1,%2,%3};"
                 : "+f"(c[0]), "+f"(c[1]), "+f"(c[2]), "+f"(c[3])
                 : "r"(a[0]), "r"(a[1]), "r"(a[2]), "r"(a[3]),
                   "r"(b[0]), "r"(b[1]));
}
__device__ __forceinline__ float tanha(float x) {
    float y; asm("tanh.approx.f32 %0, %1;" : "=f"(y) : "f"(x)); return y;
}
__device__ __forceinline__ float siga(float x) { return fmaf(0.5f, tanha(0.5f * x), 0.5f); }
__device__ __forceinline__ unsigned ld_acq(const unsigned* p) {
    unsigned v; asm volatile("ld.acquire.gpu.global.u32 %0, [%1];" : "=r"(v) : "l"(p)); return v;
}
__device__ __forceinline__ void red_rel(unsigned* p) {
    asm volatile("red.release.gpu.global.add.u32 [%0], 1;" :: "l"(p) : "memory");
}
__device__ __forceinline__ uint4 ldcg_u4(const uint4* p) {
    uint4 v;
    asm volatile("ld.global.cg.v4.u32 {%0,%1,%2,%3}, [%4];"
                 : "=r"(v.x), "=r"(v.y), "=r"(v.z), "=r"(v.w) : "l"(p));
    return v;
}

// ---------------- prep: weight convert + embed + sync zero, one launch ----------
__global__ void k_prep(const float* __restrict__ w0, const float* __restrict__ w1,
                       const int* __restrict__ inp, const float* __restrict__ emb) {
    int n = blockIdx.x;
    if (n == 0) {
        for (int i = threadIdx.x; i < 1280; i += blockDim.x) g_sync[i] = 0u;
    }
    if (n < NGATE) {                       // convert wih0 (padded)
        __half* o = g_w0h + n * K0P;
        const float* s = w0 + n * 300;
        for (int k = threadIdx.x; k < K0P; k += blockDim.x)
            o[k] = (k < 300) ? __float2half(s[k]) : __half(0.f);
    } else if (n < 2 * NGATE) {            // convert wih1
        int r = n - NGATE;
        __half* o = g_w1h + r * 512;
        const float* s = w1 + r * 512;
        for (int k = threadIdx.x; k < 512; k += blockDim.x)
            o[k] = __float2half(s[k]);
    } else {                               // embed
        int m = n - 2 * NGATE;             // m = t*64 + b
        int t = m >> 6, b = m & 63;
        int idx = inp[b * T_SEQ + t];
        const float* e = emb + (size_t)idx * 300;
        __half* o = g_x0h + (size_t)m * K0P;
        for (int k = threadIdx.x; k < K0P; k += blockDim.x)
            o[k] = (k < 300) ? __float2half(e[k]) : __half(0.f);
    }
}

// ---------------- GEMM epilogue: store to scan-friendly fp16 gates layout ----------
__device__ __forceinline__ void gates_store(float c[4][4][4], const float* bi,
                                            const float* bh, int m0, int n0,
                                            int warp_m, int warp_n, int lane,
                                            uint32_t* gout) {
#pragma unroll
    for (int nt = 0; nt < 4; nt++) {
        int n = n0 + warp_n * 32 + nt * 8 + (lane & 3) * 2;
        int dir = n >> 10, g = (n >> 8) & 3, j = n & 255;
        int blk = dir * 32 + (j >> 3), u = j & 7;
        float b0 = bi[n] + bh[n], b1 = bi[n + 1] + bh[n + 1];
        int inner = g * 4 + (u >> 1);          // u32 index within 16
#pragma unroll
        for (int mt = 0; mt < 4; mt++) {
            int r0 = m0 + warp_m * 64 + mt * 16 + (lane >> 2);
            int t = r0 >> 6, bb = r0 & 63;
            size_t base = ((size_t)(blk * 256 + t) * 64);
            gout[(base + bb) * 16 + inner]     = pk_h2(c[mt][nt][0] + b0, c[mt][nt][1] + b1);
            gout[(base + bb + 8) * 16 + inner] = pk_h2(c[mt][nt][2] + b0, c[mt][nt][3] + b1);
        }
    }
}

// ---------------- role: fp16 GEMM layer 0 (A = g_x0h via smem) ----------------
__device__ void gemm0_role(int gb, const float* bi, const float* bh, char* sbuf) {
    constexpr int K = K0P;
    constexpr int NST = K / 16;
    const __half* A = g_x0h;
    const __half* W = g_w0h;
    uint32_t* As = (uint32_t*)sbuf;       // [2][1024]
    uint32_t* Bs = As + 2048;             // [2][1024]

    const int tid = threadIdx.x, lane = tid & 31, wid = tid >> 5;
    const int by = gb >> 4, bx = gb & 15;
    const int m0 = by << 7, n0 = bx << 7;
    const int warp_m = wid & 1, warp_n = wid >> 1;

    const __half *agp[2], *wgp[2];
    int aoff[2], boff[2];
#pragma unroll
    for (int e = 0; e < 2; e++) {
        int q = tid * 2 + e, row = q >> 2, kq = q & 3;
        agp[e] = A + (size_t)(m0 + row) * K + (kq << 2);
        wgp[e] = W + (size_t)(n0 + row) * K + (kq << 2);
        int p0 = kq * 2;
        aoff[e] = (((row >> 4) * 4 + (((row >> 3) & 1) | ((p0 >> 2) << 1))) << 5)
                + ((row & 7) << 2) + (p0 & 3);
        boff[e] = (((row >> 3) * 2 + (p0 >> 2)) << 5) + ((row & 7) << 2) + (p0 & 3);
    }

    float c[4][4][4];
#pragma unroll
    for (int i = 0; i < 4; i++)
#pragma unroll
        for (int j = 0; j < 4; j++)
#pragma unroll
            for (int q = 0; q < 4; q++) c[i][j][q] = 0.f;

#pragma unroll
    for (int e = 0; e < 2; e++) {
        *(uint2*)&As[aoff[e]] = *(const uint2*)agp[e];
        *(uint2*)&Bs[boff[e]] = *(const uint2*)wgp[e];
    }
    __syncthreads();

    int buf = 0;
#pragma unroll 1
    for (int s = 0; s < NST; s++) {
        uint2 va[2], vb[2];
        const bool more = (s + 1) < NST;
        if (more) {
#pragma unroll
            for (int e = 0; e < 2; e++) {
                va[e] = *(const uint2*)(agp[e] + (s + 1) * 16);
                vb[e] = *(const uint2*)(wgp[e] + (s + 1) * 16);
            }
        }
        uint32_t af[4][4], bf[4][2];
#pragma unroll
        for (int mt = 0; mt < 4; mt++) {
            int tb = buf * 1024 + ((warp_m * 4 + mt) << 7) + lane;
#pragma unroll
            for (int r = 0; r < 4; r++) af[mt][r] = As[tb + (r << 5)];
        }
#pragma unroll
        for (int nt = 0; nt < 4; nt++) {
            int tb = buf * 1024 + ((warp_n * 4 + nt) << 6) + lane;
            bf[nt][0] = Bs[tb];
            bf[nt][1] = Bs[tb + 32];
        }
#pragma unroll
        for (int mt = 0; mt < 4; mt++)
#pragma unroll
            for (int nt = 0; nt < 4; nt++)
                mma16h(c[mt][nt], af[mt], bf[nt]);

        if (more) {
            int nb = buf ^ 1;
#pragma unroll
            for (int e = 0; e < 2; e++) {
                *(uint2*)&As[nb * 1024 + aoff[e]] = va[e];
                *(uint2*)&Bs[nb * 1024 + boff[e]] = vb[e];
            }
            __syncthreads();
            buf = nb;
        }
    }
    gates_store(c, bi, bh, m0, n0, warp_m, warp_n, lane, (uint32_t*)g_gates0h);
    __syncthreads();                       // all stores issued block-wide
    if (tid == 0) red_rel(&g_sync[1024 + by]);
}

// ---------------- role: fp16 GEMM layer 1 (A = h0 history fragments) ----------------
__device__ void gemm1_role(int gb, const float* bi, const float* bh, char* sbuf) {
    constexpr int NST = 32;   // K = 512
    const __half* W = g_w1h;
    uint32_t* Bs = (uint32_t*)sbuf;       // [2][1024]

    const int tid = threadIdx.x, lane = tid & 31, wid = tid >> 5;
    const int by = gb >> 4, bx = gb & 15;
    const int m0 = by << 7, n0 = bx << 7;
    const int warp_m = wid & 1, warp_n = wid >> 1;

    // wait for h0 of both dirs through t = 2by+1
    if (tid == 0) {
        while (ld_acq(&g_sync[2 * by + 1]) < NBLK_DIR) {}
        while (ld_acq(&g_sync[256 + 2 * by + 1]) < NBLK_DIR) {}
    }
    __syncthreads();

    const __half* wgp[2];
    int boff[2];
#pragma unroll
    for (int e = 0; e < 2; e++) {
        int q = tid * 2 + e, row = q >> 2, kq = q & 3;
        wgp[e] = W + (size_t)(n0 + row) * 512 + (kq << 2);
        int p0 = kq * 2;
        boff[e] = (((row >> 3) * 2 + (p0 >> 2)) << 5) + ((row & 7) << 2) + (p0 & 3);
    }

    const int ty0 = 2 * by;
    auto aptr = [&](int kt, int mt) -> const uint4* {
        int idx = warp_m * 4 + mt;
        return (const uint4*)(g_hb0
            + ((size_t)((kt >> 4) * 256 + ty0 + (idx >> 2)) << 13)
            + (((kt & 15) * 4 + (idx & 3)) << 7)) + lane;
    };

    float c[4][4][4];
#pragma unroll
    for (int i = 0; i < 4; i++)
#pragma unroll
        for (int j = 0; j < 4; j++)
#pragma unroll
            for (int q = 0; q < 4; q++) c[i][j][q] = 0.f;

#pragma unroll
    for (int e = 0; e < 2; e++)
        *(uint2*)&Bs[boff[e]] = *(const uint2*)wgp[e];
    uint4 afc[4];
#pragma unroll
    for (int mt = 0; mt < 4; mt++) afc[mt] = ldcg_u4(aptr(0, mt));
    __syncthreads();

    int buf = 0;
#pragma unroll 1
    for (int s = 0; s < NST; s++) {
        uint2 vb[2];
        uint4 afn[4];
        const bool more = (s + 1) < NST;
        if (more) {
#pragma unroll
            for (int e = 0; e < 2; e++) vb[e] = *(const uint2*)(wgp[e] + (s + 1) * 16);
#pragma unroll
            for (int mt = 0; mt < 4; mt++) afn[mt] = ldcg_u4(aptr(s + 1, mt));
        }
        uint32_t bf[4][2];
#pragma unroll
        for (int nt = 0; nt < 4; nt++) {
            int tb = buf * 1024 + ((warp_n * 4 + nt) << 6) + lane;
            bf[nt][0] = Bs[tb];
            bf[nt][1] = Bs[tb + 32];
        }
#pragma unroll
        for (int mt = 0; mt < 4; mt++) {
            uint32_t af[4] = { afc[mt].x, afc[mt].y, afc[mt].z, afc[mt].w };
#pragma unroll
            for (int nt = 0; nt < 4; nt++)
                mma16h(c[mt][nt], af, bf[nt]);
        }
        if (more) {
            int nb = buf ^ 1;
#pragma unroll
            for (int e = 0; e < 2; e++) *(uint2*)&Bs[nb * 1024 + boff[e]] = vb[e];
            __syncthreads();
            buf = nb;
#pragma unroll
            for (int mt = 0; mt < 4; mt++) afc[mt] = afn[mt];
        }
    }
    gates_store(c, bi, bh, m0, n0, warp_m, warp_n, lane, (uint32_t*)g_gates1h);
    __syncthreads();
    if (tid == 0) red_rel(&g_sync[1152 + by]);
}

// ---------------- role: recurrent scan (R12-proven) ----------------
__device__ void lstm_role(int layer, int lbid, const float* __restrict__ whh, char* sbuf) {
    uint32_t* gsm = (uint32_t*)sbuf;                 // [2][64*17]
    float* psum = (float*)(sbuf + 2 * 1088 * 4);     // [4*32*68]

    const int tid = threadIdx.x, lane = tid & 31, wid = tid >> 5;
    const int dir = lbid >> 5;
    const int j0  = (lbid & 31) << 3;     // 8 hidden units per block
    const int mh  = wid >> 2;             // batch half
    const int kq  = wid & 3;              // k quarter
    unsigned* barp = g_sync + layer * 512 + dir * 256;
    unsigned* gcnt = g_sync + 1024 + layer * 128;
    uint32_t* hist = layer ? g_hb1 : g_hb0;

    // persistent B fragments: W^T slice, fp16, 32 regs.  psum row nn = u*4 + g
    uint32_t bfr[4][4][2];
    {
        const int nr = lane >> 2, kl2 = (lane & 3) * 2;
#pragma unroll
        for (int nt = 0; nt < 4; nt++) {
            int nn = nt * 8 + nr;
            int row = dir * 1024 + (nn & 3) * 256 + j0 + (nn >> 2);
            const float* wr = whh + (size_t)row * 256 + kq * 64 + kl2;
#pragma unroll
            for (int kt = 0; kt < 4; kt++) {
                bfr[nt][kt][0] = pk_h2(wr[kt * 16],     wr[kt * 16 + 1]);
                bfr[nt][kt][1] = pk_h2(wr[kt * 16 + 8], wr[kt * 16 + 9]);
            }
        }
    }

    const int p = tid >> 6, b = tid & 63;
    float cst0 = 0.f, cst1 = 0.f;
    uint32_t* pub = hist + ((size_t)(dir * 256) << 13)
                  + (((j0 >> 4) * 4 + (b >> 4)) << 7)
                  + (((b & 7) << 2) + p) * 4
                  + (((b & 8) >> 3) + ((j0 & 8) >> 2));
    const uint4* gb4 = (const uint4*)(layer ? g_gates1h : g_gates0h)
                     + (size_t)(lbid * 256) * 256;

    // prologue: wait for gates(t=0,1) then stage gin(0)
    if (tid == 0) { while (ld_acq(&gcnt[0]) < 16) {} }
    __syncthreads();
    {
        uint4 g4 = __ldg(gb4 + tid);
        uint32_t* gd = gsm + (tid >> 2) * 17 + (tid & 3) * 4;
        gd[0] = g4.x; gd[1] = g4.y; gd[2] = g4.z; gd[3] = g4.w;
    }

    for (int t = 0; t < T_SEQ; t++) {
        // ensure gates for t+1 are produced (new t-pair every odd t); guard
        // t+1 < T_SEQ: at t=255 index 128 would be OOB (the R11 hang)
        if ((t & 1) && (t + 1) < T_SEQ) {
            if (tid == 0) { while (ld_acq(&gcnt[(t + 1) >> 1]) < 16) {} }
            __syncthreads();
        }
        // prefetch gin(t+1) and stage into the other buffer
        {
            int tn = (t + 1 < T_SEQ) ? t + 1 : T_SEQ - 1;
            uint4 g4 = __ldg(gb4 + tn * 256 + tid);
            uint32_t* gd = gsm + ((t + 1) & 1) * 1088 + (tid >> 2) * 17 + (tid & 3) * 4;
            gd[0] = g4.x; gd[1] = g4.y; gd[2] = g4.z; gd[3] = g4.w;
        }

        if (t > 0) {
            // wait for all dir-mates to publish h(t-1)
            while (ld_acq(&barp[t - 1]) < NBLK_DIR) {}
            const uint4* hb = (const uint4*)(hist + ((size_t)(dir * 256 + t - 1) << 13));
            uint4 aq[2][4];
#pragma unroll
            for (int kt = 0; kt < 4; kt++)
#pragma unroll
                for (int mt = 0; mt < 2; mt++)
                    aq[mt][kt] = ldcg_u4(hb + (((kq * 4 + kt) * 4 + mh * 2 + mt) << 5) + lane);

            float acc[2][4][4];
#pragma unroll
            for (int i = 0; i < 2; i++)
#pragma unroll
                for (int j = 0; j < 4; j++)
#pragma unroll
                    for (int q = 0; q < 4; q++) acc[i][j][q] = 0.f;
#pragma unroll
            for (int kt = 0; kt < 4; kt++)
#pragma unroll
                for (int mt = 0; mt < 2; mt++) {
                    uint32_t au[4] = { aq[mt][kt].x, aq[mt][kt].y, aq[mt][kt].z, aq[mt][kt].w };
#pragma unroll
                    for (int nt = 0; nt < 4; nt++)
                        mma16h(acc[mt][nt], au, bfr[nt][kt]);
                }
#pragma unroll
            for (int mt = 0; mt < 2; mt++)
#pragma unroll
                for (int nt = 0; nt < 4; nt++) {
                    int n0 = nt * 8 + (lane & 3) * 2;
                    int bb = mh * 32 + mt * 16 + (lane >> 2);
                    float* pp = psum + (kq * 32 + n0) * 68 + bb;
                    pp[0]      = acc[mt][nt][0];
                    pp[68]     = acc[mt][nt][1];
                    pp[8]      = acc[mt][nt][2];
                    pp[68 + 8] = acc[mt][nt][3];
                }
        }
        __syncthreads();   // psum + gsm(t) ready

        // gate math for units 2p, 2p+1 of batch b
        float v[4][2];
#pragma unroll
        for (int g = 0; g < 4; g++) {
            __half2 hv = *(__half2*)&gsm[(t & 1) * 1088 + b * 17 + g * 4 + p];
            float2 f2 = __half22float2(hv);
            v[g][0] = f2.x; v[g][1] = f2.y;
        }
        if (t > 0) {
            // psum row for (unit u, gate g): nn = u*4 + g; units 2p and 2p+1
#pragma unroll
            for (int g = 0; g < 4; g++) {
                int r0 = 8 * p + g;
#pragma unroll
                for (int q = 0; q < 4; q++) {
                    v[g][0] += psum[(q * 32 + r0) * 68 + b];
                    v[g][1] += psum[(q * 32 + r0 + 4) * 68 + b];
                }
            }
        }
        float h0, h1;
        {
            float ci = siga(v[0][0]), cf = siga(v[1][0]), cg = tanha(v[2][0]), co = siga(v[3][0]);
            cst0 = cf * cst0 + ci * cg;
            h0 = co * tanha(cst0);
            ci = siga(v[0][1]); cf = siga(v[1][1]); cg = tanha(v[2][1]); co = siga(v[3][1]);
            cst1 = cf * cst1 + ci * cg;
            h1 = co * tanha(cst1);
        }
        pub[(size_t)t << 13] = pk_h2(h0, h1);
        __syncthreads();   // all publish STGs issued
        if (tid == 0) red_rel(&barp[t]);   // signal EVERY t (gemm1 needs t=255)
    }
}

// ---------------- fused pipeline kernel ----------------
__global__ __launch_bounds__(256, 2) void k_fused(const float* __restrict__ bih0,
                                                  const float* __restrict__ bhh0,
                                                  const float* __restrict__ bih1,
                                                  const float* __restrict__ bhh1,
                                                  const float* __restrict__ whh0,
                                                  const float* __restrict__ whh1) {
    __shared__ __align__(16) char sbuf[43520];
    const int bid = blockIdx.x;
    if (bid < 64) {
        lstm_role(0, bid, whh0, sbuf);
    } else if (bid < 128) {
        lstm_role(1, bid - 64, whh1, sbuf);
    } else {
        int g = bid - GEMM_BASE;
        int by = g >> 5, r = g & 31;
        if (r < 16) gemm0_role((by << 4) | r,        bih0, bhh0, sbuf);
        else        gemm1_role((by << 4) | (r - 16), bih1, bhh1, sbuf);
    }
}

// ---------------- classifier: gather from layer-1 history ----------------
__global__ void k_clf(const int* __restrict__ tidx, const float* __restrict__ cw,
                      const float* __restrict__ cb, float* __restrict__ out) {
    __shared__ float red[128];
    int b = blockIdx.x;
    int t = tidx[b];
    const __half* hist = (const __half*)g_hb1;
    float s = 0.f;
    for (int f = threadIdx.x; f < 512; f += 128) {
        int dir = f >> 8, u = f & 255;
        int ut = u >> 4, k16 = u & 15;
        int l = ((b & 7) << 2) + ((k16 & 7) >> 1);
        int sl = ((b & 8) >> 3) + ((k16 & 8) >> 2);
        size_t u32i = ((size_t)(dir * 256 + t) << 13) + (((ut << 2) + (b >> 4)) << 7)
                    + l * 4 + sl;
        s += __half2float(hist[u32i * 2 + (k16 & 1)]) * cw[f];
    }
    red[threadIdx.x] = s;
    __syncthreads();
    for (int off = 64; off > 0; off >>= 1) {
        if (threadIdx.x < off) red[threadIdx.x] += red[threadIdx.x + off];
        __syncthreads();
    }
    if (threadIdx.x == 0) out[b] = 1.f / (1.f + expf(-(red[0] + cb[0])));
}

// ---------------- host ----------------
extern "C" void kernel_launch(void* const* d_in, const int* in_sizes, int n_in,
                              void* d_out, int out_size) {
    const int*   inp  = (const int*)  d_in[0];
    const int*   tidx = (const int*)  d_in[1];
    const float* emb  = (const float*)d_in[2];
    const float* wih0 = (const float*)d_in[3];
    const float* whh0 = (const float*)d_in[4];
    const float* bih0 = (const float*)d_in[5];
    const float* bhh0 = (const float*)d_in[6];
    const float* wih1 = (const float*)d_in[7];
    const float* whh1 = (const float*)d_in[8];
    const float* bih1 = (const float*)d_in[9];
    const float* bhh1 = (const float*)d_in[10];
    const float* clfw = (const float*)d_in[11];
    const float* clfb = (const float*)d_in[12];
    float* out = (float*)d_out;

    // one prep launch: weight converts + embed + sync zero (all independent)
    k_prep<<<2 * NGATE + MROWS, 128>>>(wih0, wih1, inp, emb);
    // fused pipeline: lstm0 | lstm1 | interleaved gemm0/gemm1, counter-chained
    k_fused<<<TOTAL_BLKS, 256>>>(bih0, bhh0, bih1, bhh1, whh0, whh1);
    k_clf<<<BATCH, 128>>>(tidx, clfw, clfb, out);
}